// round 8
// baseline (speedup 1.0000x reference)
#include <cuda_runtime.h>
#include <cstdint>

#define BATCH  64
#define MROWS  2048
#define DIM    512
#define CHUNKS 64            // MROWS / 32 rows-per-block

// Per-(batch,chunk) packed partial: (dist2_bits << 32) | (0xFFFFFFFF - m).
// Every slot is written every launch -> no init kernel needed.
__device__ unsigned long long g_part[BATCH * CHUNKS];
// Per-batch completion counter; last block resets it to 0 (graph-replay safe).
__device__ unsigned int g_count[BATCH];

static __device__ __forceinline__ unsigned long long umax64(
    unsigned long long a, unsigned long long b) { return a > b ? a : b; }

// Grid: (CHUNKS, BATCH). Block: 256 threads = 8 warps; each warp handles 4 rows.
// Double-buffered row prefetch keeps 4 LDG.128/warp in flight across the
// FMA+SHFL reduce chain; query stays in smem to fit the 64-reg / 4-CTA budget.
__global__ __launch_bounds__(256, 4) void knn_fused_kernel(
    const float* __restrict__ inputs,
    const float* __restrict__ buffer,
    float* __restrict__ out)
{
    __shared__ float4 q4s[DIM / 4];              // 2 KB query
    __shared__ unsigned long long wbest[8];
    __shared__ unsigned int s_is_last;
    __shared__ unsigned int s_m;

    const int b     = blockIdx.y;
    const int chunk = blockIdx.x;
    const int tid   = threadIdx.x;
    const int warp  = tid >> 5;
    const int lane  = tid & 31;

    // Stage query into smem (coalesced float4).
    const float4* qin = reinterpret_cast<const float4*>(inputs + (size_t)b * DIM);
    for (int i = tid; i < DIM / 4; i += blockDim.x) q4s[i] = qin[i];
    __syncthreads();

    const int m0 = chunk * 32 + warp * 4;
    const float* base = buffer + ((size_t)b * MROWS + m0) * DIM;

    // Prefetch row 0.
    float4 va[4], vb[4];
    {
        const float4* r0 = reinterpret_cast<const float4*>(base);
        #pragma unroll
        for (int j = 0; j < 4; j++) va[j] = r0[lane + 32 * j];
    }

    unsigned long long local = 0ULL;
    #pragma unroll
    for (int k = 0; k < 4; k++) {
        // Prefetch row k+1 while computing row k.
        if (k < 3) {
            const float4* rn =
                reinterpret_cast<const float4*>(base + (size_t)(k + 1) * DIM);
            #pragma unroll
            for (int j = 0; j < 4; j++) vb[j] = rn[lane + 32 * j];
        }

        float acc0 = 0.0f, acc1 = 0.0f, acc2 = 0.0f, acc3 = 0.0f;
        #pragma unroll
        for (int j = 0; j < 4; j++) {
            float4 q = q4s[lane + 32 * j];       // LDS.128, conflict-free
            float4 v = va[j];
            float d0 = v.x - q.x;
            float d1 = v.y - q.y;
            float d2 = v.z - q.z;
            float d3 = v.w - q.w;
            acc0 = fmaf(d0, d0, acc0);
            acc1 = fmaf(d1, d1, acc1);
            acc2 = fmaf(d2, d2, acc2);
            acc3 = fmaf(d3, d3, acc3);
        }
        float acc = (acc0 + acc1) + (acc2 + acc3);

        #pragma unroll
        for (int off = 16; off > 0; off >>= 1)
            acc += __shfl_xor_sync(0xFFFFFFFFu, acc, off);

        // dist2 >= 0 -> float bits order-preserving; ~m tie-breaks to smallest m.
        unsigned long long pack =
            ((unsigned long long)__float_as_uint(acc) << 32) |
            (unsigned long long)(0xFFFFFFFFu - (unsigned)(m0 + k));
        local = umax64(local, pack);

        // Rotate buffers (register-renamed away under full unroll).
        #pragma unroll
        for (int j = 0; j < 4; j++) va[j] = vb[j];
    }

    if (lane == 0) wbest[warp] = local;
    __syncthreads();

    // ---- Block reduce + completion protocol ----
    if (tid == 0) {
        unsigned long long blk = wbest[0];
        #pragma unroll
        for (int w = 1; w < 8; w++) blk = umax64(blk, wbest[w]);
        g_part[b * CHUNKS + chunk] = blk;
        __threadfence();                          // publish partial before count
        unsigned int old = atomicAdd(&g_count[b], 1u);
        s_is_last = (old == CHUNKS - 1) ? 1u : 0u;
    }
    __syncthreads();

    // ---- Last block for this batch: reduce partials + gather winning row ----
    if (s_is_last) {
        if (warp == 0) {
            __threadfence();                      // acquire partials
            unsigned long long a = g_part[b * CHUNKS + lane];
            unsigned long long c = g_part[b * CHUNKS + 32 + lane];
            unsigned long long mx = umax64(a, c);
            #pragma unroll
            for (int off = 16; off > 0; off >>= 1) {
                unsigned long long o = __shfl_xor_sync(0xFFFFFFFFu, mx, off);
                mx = umax64(mx, o);
            }
            if (lane == 0) {
                s_m = 0xFFFFFFFFu - (unsigned)(mx & 0xFFFFFFFFu);
                g_count[b] = 0;                   // restore invariant for next replay
            }
        }
        __syncthreads();
        const unsigned m = s_m;
        const float4* src = reinterpret_cast<const float4*>(
            buffer + ((size_t)b * MROWS + m) * DIM);
        float4* dst = reinterpret_cast<float4*>(out + (size_t)b * DIM);
        if (tid < DIM / 4) dst[tid] = src[tid];
    }
}

extern "C" void kernel_launch(void* const* d_in, const int* in_sizes, int n_in,
                              void* d_out, int out_size)
{
    const float* inputs = (const float*)d_in[0];   // [B, D]
    const float* buffer = (const float*)d_in[1];   // [B, M, D]
    float* out = (float*)d_out;                    // [B, D]

    dim3 grid(CHUNKS, BATCH);                      // 64 x 64 = 4096 blocks
    knn_fused_kernel<<<grid, 256>>>(inputs, buffer, out);
}

// round 9
// speedup vs baseline: 1.0801x; 1.0801x over previous
#include <cuda_runtime.h>
#include <cstdint>

#define BATCH  64
#define MROWS  2048
#define DIM    512
#define NCHUNK 64            // MROWS / 32 rows-per-chunk
#define NSEG   9             // blocks per batch

// Per-(batch,seg) packed partial: (dist2_bits << 32) | (0xFFFFFFFF - m).
// Every slot is written every launch -> no init kernel needed.
__device__ unsigned long long g_part[BATCH * NSEG];
// Per-batch completion counter; last block resets it to 0 (graph-replay safe).
__device__ unsigned int g_count[BATCH];

static __device__ __forceinline__ unsigned long long umax64(
    unsigned long long a, unsigned long long b) { return a > b ? a : b; }

// Grid: BATCH*NSEG = 576 blocks -> single wave at occ 4 (592 slots).
// Each block serves one batch and loops chunks {seg, seg+9, ...} < 64,
// amortizing the query stage + block startup over ~8 chunks (~512 KB stream).
__global__ __launch_bounds__(256, 4) void knn_fused_kernel(
    const float* __restrict__ inputs,
    const float* __restrict__ buffer,
    float* __restrict__ out)
{
    __shared__ float4 q4s[DIM / 4];              // 2 KB query
    __shared__ unsigned long long wbest[8];
    __shared__ unsigned int s_is_last;
    __shared__ unsigned int s_m;

    const int bx   = blockIdx.x;
    const int b    = bx / NSEG;
    const int seg  = bx % NSEG;
    const int tid  = threadIdx.x;
    const int warp = tid >> 5;
    const int lane = tid & 31;

    // Stage query into smem once per block (coalesced float4).
    const float4* qin = reinterpret_cast<const float4*>(inputs + (size_t)b * DIM);
    for (int i = tid; i < DIM / 4; i += blockDim.x) q4s[i] = qin[i];
    __syncthreads();

    const float* buf_b = buffer + (size_t)b * MROWS * DIM;

    unsigned long long local = 0ULL;

    for (int chunk = seg; chunk < NCHUNK; chunk += NSEG) {
        const int m0 = chunk * 32 + warp * 4;
        const float* base = buf_b + (size_t)m0 * DIM;

        // Prefetch row 0 of this chunk.
        float4 va[4], vb[4];
        {
            const float4* r0 = reinterpret_cast<const float4*>(base);
            #pragma unroll
            for (int j = 0; j < 4; j++) va[j] = r0[lane + 32 * j];
        }

        #pragma unroll
        for (int k = 0; k < 4; k++) {
            // Prefetch row k+1 while computing row k.
            if (k < 3) {
                const float4* rn =
                    reinterpret_cast<const float4*>(base + (size_t)(k + 1) * DIM);
                #pragma unroll
                for (int j = 0; j < 4; j++) vb[j] = rn[lane + 32 * j];
            }

            float acc0 = 0.0f, acc1 = 0.0f, acc2 = 0.0f, acc3 = 0.0f;
            #pragma unroll
            for (int j = 0; j < 4; j++) {
                float4 q = q4s[lane + 32 * j];   // LDS.128, conflict-free
                float4 v = va[j];
                float d0 = v.x - q.x;
                float d1 = v.y - q.y;
                float d2 = v.z - q.z;
                float d3 = v.w - q.w;
                acc0 = fmaf(d0, d0, acc0);
                acc1 = fmaf(d1, d1, acc1);
                acc2 = fmaf(d2, d2, acc2);
                acc3 = fmaf(d3, d3, acc3);
            }
            float acc = (acc0 + acc1) + (acc2 + acc3);

            #pragma unroll
            for (int off = 16; off > 0; off >>= 1)
                acc += __shfl_xor_sync(0xFFFFFFFFu, acc, off);

            // dist2 >= 0 -> float bits order-preserving; ~m tie-breaks to
            // the smallest m (argmax first-index semantics).
            unsigned long long pack =
                ((unsigned long long)__float_as_uint(acc) << 32) |
                (unsigned long long)(0xFFFFFFFFu - (unsigned)(m0 + k));
            local = umax64(local, pack);

            #pragma unroll
            for (int j = 0; j < 4; j++) va[j] = vb[j];
        }
    }

    if (lane == 0) wbest[warp] = local;
    __syncthreads();

    // ---- Block reduce + completion protocol ----
    if (tid == 0) {
        unsigned long long blk = wbest[0];
        #pragma unroll
        for (int w = 1; w < 8; w++) blk = umax64(blk, wbest[w]);
        g_part[b * NSEG + seg] = blk;
        __threadfence();                          // publish partial before count
        unsigned int old = atomicAdd(&g_count[b], 1u);
        s_is_last = (old == NSEG - 1) ? 1u : 0u;
    }
    __syncthreads();

    // ---- Last block for this batch: reduce 9 partials + gather winning row ----
    if (s_is_last) {
        if (warp == 0) {
            __threadfence();                      // acquire partials
            unsigned long long mx =
                (lane < NSEG) ? g_part[b * NSEG + lane] : 0ULL;
            #pragma unroll
            for (int off = 16; off > 0; off >>= 1) {
                unsigned long long o = __shfl_xor_sync(0xFFFFFFFFu, mx, off);
                mx = umax64(mx, o);
            }
            if (lane == 0) {
                s_m = 0xFFFFFFFFu - (unsigned)(mx & 0xFFFFFFFFu);
                g_count[b] = 0;                   // restore invariant for next replay
            }
        }
        __syncthreads();
        const unsigned m = s_m;
        const float4* src = reinterpret_cast<const float4*>(
            buffer + ((size_t)b * MROWS + m) * DIM);
        float4* dst = reinterpret_cast<float4*>(out + (size_t)b * DIM);
        if (tid < DIM / 4) dst[tid] = src[tid];
    }
}

extern "C" void kernel_launch(void* const* d_in, const int* in_sizes, int n_in,
                              void* d_out, int out_size)
{
    const float* inputs = (const float*)d_in[0];   // [B, D]
    const float* buffer = (const float*)d_in[1];   // [B, M, D]
    float* out = (float*)d_out;                    // [B, D]

    knn_fused_kernel<<<BATCH * NSEG, 256>>>(inputs, buffer, out);
}